// round 7
// baseline (speedup 1.0000x reference)
#include <cuda_runtime.h>
#include <stdint.h>
#include <math.h>

// ---------------------------------------------------------------------------
// Problem constants
// ---------------------------------------------------------------------------
#define BATCH   2
#define LSEQ    2048
#define DIMC    256
#define DI      512          // d_inner
#define DS      64           // d_state
#define DTR     16           // dt_rank
#define XDBLW   144          // dt_rank + 2*d_state
#define NTOK    (BATCH*LSEQ) // 4096
#define SQRT_INV_8192 0.011048543456039806f
#define LAMBDA_SS 0.01f
#define PI_F 3.14159265358979323846f

// ---------------------------------------------------------------------------
// Scratch (single __device__ array; no allocations anywhere)
// ---------------------------------------------------------------------------
#define O_XN    ((size_t)0)
#define O_XZ    (O_XN   + (size_t)NTOK*DIMC)
#define O_XC    (O_XZ   + (size_t)NTOK*2*DI)
#define O_XDBL  (O_XC   + (size_t)NTOK*DI)
#define O_Y     (O_XDBL + (size_t)NTOK*XDBLW)
#define O_X1    (O_Y    + (size_t)NTOK*DI)
#define O_XN2   (O_X1   + (size_t)NTOK*DIMC)
#define O_FR    (O_XN2  + (size_t)NTOK*DIMC)
#define O_FI    (O_FR   + (size_t)NTOK*DIMC)
#define O_END   (O_FI   + (size_t)NTOK*DIMC)

__device__ float SCRATCH[O_END];

// ---------------------------------------------------------------------------
// cp.async helpers
// ---------------------------------------------------------------------------
__device__ __forceinline__ void cp16(unsigned dst, const void* src, int sz) {
    asm volatile("cp.async.cg.shared.global [%0], [%1], 16, %2;"
                 :: "r"(dst), "l"(src), "r"(sz));
}
__device__ __forceinline__ void cp_commit() {
    asm volatile("cp.async.commit_group;" ::: "memory");
}
template <int N>
__device__ __forceinline__ void cp_wait() {
    asm volatile("cp.async.wait_group %0;" :: "n"(N) : "memory");
}

// ---------------------------------------------------------------------------
// LayerNorm: one warp per token (256 channels), 8 tokens per 256-thread block
// ---------------------------------------------------------------------------
__global__ void ln_kernel(const float* __restrict__ x,
                          const float* __restrict__ w,
                          const float* __restrict__ b,
                          float* __restrict__ out) {
    int t = blockIdx.x * 8 + (threadIdx.x >> 5);
    int lane = threadIdx.x & 31;
    const float4* row = (const float4*)(x + (size_t)t * DIMC);
    float4 v0 = row[lane];
    float4 v1 = row[lane + 32];
    float s = v0.x + v0.y + v0.z + v0.w + v1.x + v1.y + v1.z + v1.w;
    #pragma unroll
    for (int off = 16; off; off >>= 1) s += __shfl_xor_sync(0xffffffffu, s, off);
    float m = s * (1.0f / 256.0f);
    float d0 = v0.x - m, d1 = v0.y - m, d2 = v0.z - m, d3 = v0.w - m;
    float d4 = v1.x - m, d5 = v1.y - m, d6 = v1.z - m, d7 = v1.w - m;
    float q = d0*d0 + d1*d1 + d2*d2 + d3*d3 + d4*d4 + d5*d5 + d6*d6 + d7*d7;
    #pragma unroll
    for (int off = 16; off; off >>= 1) q += __shfl_xor_sync(0xffffffffu, q, off);
    float inv = rsqrtf(q * (1.0f / 256.0f) + 1e-5f);
    const float4* w4 = (const float4*)w;
    const float4* b4 = (const float4*)b;
    float4* o4 = (float4*)(out + (size_t)t * DIMC);
    float4 wa = w4[lane], ba = b4[lane];
    float4 wb = w4[lane + 32], bb = b4[lane + 32];
    float4 r0, r1;
    r0.x = d0*inv*wa.x + ba.x; r0.y = d1*inv*wa.y + ba.y;
    r0.z = d2*inv*wa.z + ba.z; r0.w = d3*inv*wa.w + ba.w;
    r1.x = d4*inv*wb.x + bb.x; r1.y = d5*inv*wb.y + bb.y;
    r1.z = d6*inv*wb.z + bb.z; r1.w = d7*inv*wb.w + bb.w;
    o4[lane] = r0; o4[lane + 32] = r1;
}

// ---------------------------------------------------------------------------
// tf32 tensor-core GEMM: C[M,N] = A[M,K] * W[N,K]^T (+ R[M,N]).
// 64x64 block tile, BK=16, 128 threads = 4 warps (2m x 2n), warp tile 32x32
// via 2x4 mma.sync.m16n8k8.tf32.  4-stage cp.async pipeline; raw fp32 bits
// fed to HMMA (hardware truncates to tf32).  M%64==0, K%16==0 guaranteed.
// ---------------------------------------------------------------------------
#define GBM 64
#define GBN 64
#define ASTR 20
#define GSTAGES 4
#define GEMM_SMEM (GSTAGES * (GBM + GBN) * ASTR * 4)

__device__ __forceinline__ void mma_tf32(float* c, const unsigned* a, const unsigned* b) {
    asm volatile(
        "mma.sync.aligned.m16n8k8.row.col.f32.tf32.tf32.f32 "
        "{%0,%1,%2,%3}, {%4,%5,%6,%7}, {%8,%9}, {%0,%1,%2,%3};"
        : "+f"(c[0]), "+f"(c[1]), "+f"(c[2]), "+f"(c[3])
        : "r"(a[0]), "r"(a[1]), "r"(a[2]), "r"(a[3]), "r"(b[0]), "r"(b[1]));
}

__global__ void __launch_bounds__(128) gemm_tf32(const float* __restrict__ A,
                                                 const float* __restrict__ W,
                                                 const float* __restrict__ R,
                                                 float* __restrict__ C,
                                                 int M, int N, int K) {
    extern __shared__ float gsm[];
    float* As = gsm;                                // GSTAGES * GBM * ASTR
    float* Bs = gsm + GSTAGES * GBM * ASTR;         // GSTAGES * GBN * ASTR
    unsigned smA = (unsigned)__cvta_generic_to_shared(As);
    unsigned smB = (unsigned)__cvta_generic_to_shared(Bs);

    int m0 = blockIdx.y * GBM;
    int n0 = blockIdx.x * GBN;
    int tid = threadIdx.x;
    int wid = tid >> 5, lane = tid & 31;
    int wm = (wid & 1) * 32;
    int wn = (wid >> 1) * 32;
    int gid = lane >> 2;       // 0..7
    int tig = lane & 3;        // 0..3
    int ar = tid >> 1, ak = (tid & 1) * 8;   // 64 rows x 16k via 2 cp16
    int br = tid >> 1, bk = (tid & 1) * 8;

    const float* Abase = A + (size_t)(m0 + ar) * K + ak;
    bool bok = (n0 + br) < N;
    const float* Bbase = bok ? (W + (size_t)(n0 + br) * K + bk) : W;
    int bsz = bok ? 16 : 0;
    unsigned adst = smA + (unsigned)(ar * ASTR + ak) * 4u;
    unsigned bdst = smB + (unsigned)(br * ASTR + bk) * 4u;
    const unsigned aStage = GBM * ASTR * 4u;
    const unsigned bStage = GBN * ASTR * 4u;

    float acc[2][4][4];
    #pragma unroll
    for (int mi = 0; mi < 2; mi++)
        #pragma unroll
        for (int ni = 0; ni < 4; ni++)
            #pragma unroll
            for (int q = 0; q < 4; q++) acc[mi][ni][q] = 0.0f;

    int nIt = K >> 4;
    // prologue: stages 0..GSTAGES-2
    #pragma unroll
    for (int s = 0; s < GSTAGES - 1; s++) {
        cp16(adst + s * aStage,      Abase + s * 16,     16);
        cp16(adst + s * aStage + 16, Abase + s * 16 + 4, 16);
        cp16(bdst + s * bStage,      Bbase + (bok ? s * 16 : 0), bsz);
        cp16(bdst + s * bStage + 16, Bbase + (bok ? s * 16 + 4 : 0), bsz);
        cp_commit();
    }

    for (int it = 0; it < nIt; it++) {
        cp_wait<GSTAGES - 2>();
        __syncthreads();
        int buf = it & (GSTAGES - 1);
        const float* Ab = As + buf * (GBM * ASTR);
        const float* Bb = Bs + buf * (GBN * ASTR);
        #pragma unroll
        for (int ks = 0; ks < 2; ks++) {
            int k8 = ks * 8;
            unsigned afr[2][4], bfr[4][2];
            #pragma unroll
            for (int mi = 0; mi < 2; mi++) {
                int rb = wm + mi * 16 + gid;
                afr[mi][0] = __float_as_uint(Ab[(rb)     * ASTR + k8 + tig]);
                afr[mi][1] = __float_as_uint(Ab[(rb + 8) * ASTR + k8 + tig]);
                afr[mi][2] = __float_as_uint(Ab[(rb)     * ASTR + k8 + tig + 4]);
                afr[mi][3] = __float_as_uint(Ab[(rb + 8) * ASTR + k8 + tig + 4]);
            }
            #pragma unroll
            for (int ni = 0; ni < 4; ni++) {
                int cb = wn + ni * 8 + gid;
                bfr[ni][0] = __float_as_uint(Bb[cb * ASTR + k8 + tig]);
                bfr[ni][1] = __float_as_uint(Bb[cb * ASTR + k8 + tig + 4]);
            }
            #pragma unroll
            for (int mi = 0; mi < 2; mi++)
                #pragma unroll
                for (int ni = 0; ni < 4; ni++)
                    mma_tf32(acc[mi][ni], afr[mi], bfr[ni]);
        }
        int nx = it + GSTAGES - 1;
        if (nx < nIt) {
            int slot = nx & (GSTAGES - 1);
            cp16(adst + slot * aStage,      Abase + nx * 16,     16);
            cp16(adst + slot * aStage + 16, Abase + nx * 16 + 4, 16);
            cp16(bdst + slot * bStage,      Bbase + (bok ? nx * 16 : 0), bsz);
            cp16(bdst + slot * bStage + 16, Bbase + (bok ? nx * 16 + 4 : 0), bsz);
        }
        cp_commit();
    }

    #pragma unroll
    for (int mi = 0; mi < 2; mi++) {
        int row = m0 + wm + mi * 16 + gid;
        #pragma unroll
        for (int ni = 0; ni < 4; ni++) {
            int col = n0 + wn + ni * 8 + tig * 2;
            if (col < N) {
                float v0 = acc[mi][ni][0];
                float v2 = acc[mi][ni][2];
                if (R) { v0 += R[(size_t)row * N + col]; v2 += R[(size_t)(row + 8) * N + col]; }
                C[(size_t)row * N + col] = v0;
                C[(size_t)(row + 8) * N + col] = v2;
            }
            if (col + 1 < N) {
                float v1 = acc[mi][ni][1];
                float v3 = acc[mi][ni][3];
                if (R) { v1 += R[(size_t)row * N + col + 1]; v3 += R[(size_t)(row + 8) * N + col + 1]; }
                C[(size_t)row * N + col + 1] = v1;
                C[(size_t)(row + 8) * N + col + 1] = v3;
            }
        }
    }
}

// ---------------------------------------------------------------------------
// Depthwise causal conv (k=4) + bias + SiLU.  xz[:, 0:512] -> xc
// ---------------------------------------------------------------------------
__global__ void conv_silu_kernel(const float* __restrict__ xz,
                                 const float* __restrict__ cw,
                                 const float* __restrict__ cb,
                                 float* __restrict__ xc) {
    int idx = blockIdx.x * 256 + threadIdx.x;   // NTOK*DI
    int d = idx & (DI - 1);
    int bt = idx >> 9;
    int b = bt >> 11;
    int l = bt & (LSEQ - 1);
    float acc = cb[d];
    #pragma unroll
    for (int k = 0; k < 4; k++) {
        int ls = l + k - 3;
        if (ls >= 0)
            acc += xz[((size_t)((b << 11) | ls)) * (2 * DI) + d] * cw[d * 4 + k];
    }
    float sg = 1.0f / (1.0f + __expf(-acc));
    xc[(size_t)bt * DI + d] = acc * sg;
}

// ---------------------------------------------------------------------------
// Selective scan with fused dt; deferred reduce-scatter for y.
// ---------------------------------------------------------------------------
#define TCHUNK 64
__global__ void __launch_bounds__(256) scan_kernel(
        const float* __restrict__ xdbl,
        const float* __restrict__ xc,
        const float* __restrict__ xz,
        const float* __restrict__ A_log,
        const float* __restrict__ Dvec,
        const float* __restrict__ dtw,
        const float* __restrict__ dtb,
        float* __restrict__ y) {
    __shared__ float sB[TCHUNK][64];
    __shared__ float sC[TCHUNK][64];
    __shared__ float sx16[TCHUNK][16];
    __shared__ float2 sdx[TCHUNK][8];   // (dt, xc)
    __shared__ float sz[TCHUNK][8];
    __shared__ float sy[TCHUNK][8];
    __shared__ float sw[8][16];
    __shared__ float sbias[8];

    int b = blockIdx.x >> 6;
    int dbase = (blockIdx.x & 63) * 8;
    int wid = threadIdx.x >> 5;
    int lane = threadIdx.x & 31;
    int d = dbase + wid;

    if (threadIdx.x < 128) {
        int di = threadIdx.x >> 4, r = threadIdx.x & 15;
        sw[di][r] = dtw[(dbase + di) * DTR + r];
        if (r == 0) sbias[di] = dtb[dbase + di];
    }
    float A0 = -__expf(A_log[d * DS + lane]);
    float A1 = -__expf(A_log[d * DS + lane + 32]);
    float Dd = Dvec[d];
    float h0 = 0.0f, h1 = 0.0f;

    for (int t0 = 0; t0 < LSEQ; t0 += TCHUNK) {
        for (int i = threadIdx.x; i < TCHUNK * 128; i += 256) {
            int tt = i >> 7;
            int c = i & 127;
            float v = xdbl[(size_t)(b * LSEQ + t0 + tt) * XDBLW + DTR + c];
            if (c < 64) sB[tt][c] = v; else sC[tt][c - 64] = v;
        }
        for (int i = threadIdx.x; i < TCHUNK * 16; i += 256) {
            int tt = i >> 4, r = i & 15;
            sx16[tt][r] = xdbl[(size_t)(b * LSEQ + t0 + tt) * XDBLW + r];
        }
        for (int i = threadIdx.x; i < TCHUNK * 8; i += 256) {
            int tt = i >> 3, di = i & 7;
            size_t bt = (size_t)(b * LSEQ + t0 + tt);
            sdx[tt][di].y = xc[bt * DI + dbase + di];
            sz[tt][di]    = xz[bt * (2 * DI) + DI + dbase + di];
        }
        __syncthreads();
        for (int i = threadIdx.x; i < TCHUNK * 8; i += 256) {
            int tt = i >> 3, di = i & 7;
            float acc = sbias[di];
            #pragma unroll
            for (int r = 0; r < 16; r++) acc = fmaf(sx16[tt][r], sw[di][r], acc);
            sdx[tt][di].x = (acc > 20.0f) ? acc : __logf(1.0f + __expf(acc));
        }
        __syncthreads();

        #pragma unroll 1
        for (int g = 0; g < TCHUNK / 32; g++) {
            float part[32];
            #pragma unroll
            for (int j = 0; j < 32; j++) {
                int tt = g * 32 + j;
                float2 dx = sdx[tt][wid];
                float du = dx.x * dx.y;
                float dA0 = __expf(dx.x * A0);
                float dA1 = __expf(dx.x * A1);
                h0 = fmaf(dA0, h0, du * sB[tt][lane]);
                h1 = fmaf(dA1, h1, du * sB[tt][lane + 32]);
                part[j] = fmaf(h0, sC[tt][lane], h1 * sC[tt][lane + 32]);
            }
            #pragma unroll
            for (int s = 16; s >= 1; s >>= 1) {
                bool up = (lane & s) != 0;
                #pragma unroll
                for (int i2 = 0; i2 < 16; i2++) {
                    if (i2 >= s) break;
                    float keep = up ? part[i2 + s] : part[i2];
                    float send = up ? part[i2] : part[i2 + s];
                    part[i2] = keep + __shfl_xor_sync(0xffffffffu, send, s);
                }
            }
            int tt = g * 32 + lane;
            float2 dx = sdx[tt][wid];
            float zv = sz[tt][wid];
            float gate = zv / (1.0f + __expf(-zv));
            sy[tt][wid] = fmaf(dx.y, Dd, part[0]) * gate;
        }
        __syncthreads();
        for (int i = threadIdx.x; i < TCHUNK * 8; i += 256) {
            int tt = i >> 3, di = i & 7;
            y[(size_t)(b * LSEQ + t0 + tt) * DI + dbase + di] = sy[tt][di];
        }
        __syncthreads();
    }
}

// ---------------------------------------------------------------------------
// Forward 2048-pt FFT (DIF, natural -> bit-reversed), real input.
// 2 channels per block (256 blocks), float2 global I/O, padded stride 2049.
// ---------------------------------------------------------------------------
#define FSTR 2049
#define FFT_SMEM (2 * 2 * FSTR * 4)

__global__ void __launch_bounds__(512) fft_fwd_kernel(const float* __restrict__ xin,
                                                      float* __restrict__ dR,
                                                      float* __restrict__ dI) {
    extern __shared__ float sm[];
    float* sr = sm;
    float* si = sm + 2 * FSTR;
    int b = blockIdx.x >> 7;
    int c0 = (blockIdx.x & 127) * 2;
    size_t base = (size_t)b * LSEQ * DIMC + c0;
    int tid = threadIdx.x;

    for (int n = tid; n < 2048; n += 512) {
        float2 v = *(const float2*)(xin + base + (size_t)n * DIMC);
        sr[0 * FSTR + n] = v.x; sr[1 * FSTR + n] = v.y;
        si[0 * FSTR + n] = 0.0f; si[1 * FSTR + n] = 0.0f;
    }
    __syncthreads();

    #pragma unroll
    for (int hb = 10; hb >= 0; hb--) {
        int half = 1 << hb;
        float th = -PI_F / (float)half;
        for (int e = tid; e < 2048; e += 512) {
            int col = e >> 10, idx = e & 1023;
            int j = idx & (half - 1);
            int pos = ((idx >> hb) << (hb + 1)) + j;
            float* cr = sr + col * FSTR;
            float* ci = si + col * FSTR;
            float ar = cr[pos],        ai = ci[pos];
            float br = cr[pos + half], bi = ci[pos + half];
            float wi, wr;
            __sincosf(th * (float)j, &wi, &wr);
            float xr = ar - br, xi = ai - bi;
            cr[pos] = ar + br;  ci[pos] = ai + bi;
            cr[pos + half] = xr * wr - xi * wi;
            ci[pos + half] = xr * wi + xi * wr;
        }
        __syncthreads();
    }

    for (int n = tid; n < 2048; n += 512) {
        float2 vr, vi;
        vr.x = sr[0 * FSTR + n]; vr.y = sr[1 * FSTR + n];
        vi.x = si[0 * FSTR + n]; vi.y = si[1 * FSTR + n];
        *(float2*)(dR + base + (size_t)n * DIMC) = vr;
        *(float2*)(dI + base + (size_t)n * DIMC) = vi;
    }
}

// ---------------------------------------------------------------------------
// Inverse 2048-pt FFT (DIT, bit-reversed -> natural); real part + residual.
// ---------------------------------------------------------------------------
__global__ void __launch_bounds__(512) fft_inv_kernel(const float* __restrict__ dR,
                                                      const float* __restrict__ dI,
                                                      const float* __restrict__ x1,
                                                      float* __restrict__ out) {
    extern __shared__ float sm[];
    float* sr = sm;
    float* si = sm + 2 * FSTR;
    int b = blockIdx.x >> 7;
    int c0 = (blockIdx.x & 127) * 2;
    size_t base = (size_t)b * LSEQ * DIMC + c0;
    int tid = threadIdx.x;

    for (int n = tid; n < 2048; n += 512) {
        float2 vr = *(const float2*)(dR + base + (size_t)n * DIMC);
        float2 vi = *(const float2*)(dI + base + (size_t)n * DIMC);
        sr[0 * FSTR + n] = vr.x; sr[1 * FSTR + n] = vr.y;
        si[0 * FSTR + n] = vi.x; si[1 * FSTR + n] = vi.y;
    }
    __syncthreads();

    #pragma unroll
    for (int hb = 0; hb <= 10; hb++) {
        int half = 1 << hb;
        float th = PI_F / (float)half;
        for (int e = tid; e < 2048; e += 512) {
            int col = e >> 10, idx = e & 1023;
            int j = idx & (half - 1);
            int pos = ((idx >> hb) << (hb + 1)) + j;
            float* cr = sr + col * FSTR;
            float* ci = si + col * FSTR;
            float ar = cr[pos],        ai = ci[pos];
            float br = cr[pos + half], bi = ci[pos + half];
            float wi, wr;
            __sincosf(th * (float)j, &wi, &wr);
            float tr = br * wr - bi * wi;
            float ti = br * wi + bi * wr;
            cr[pos] = ar + tr;         ci[pos] = ai + ti;
            cr[pos + half] = ar - tr;  ci[pos + half] = ai - ti;
        }
        __syncthreads();
    }

    for (int n = tid; n < 2048; n += 512) {
        size_t a = base + (size_t)n * DIMC;
        float2 rx = *(const float2*)(x1 + a);
        float2 o;
        o.x = rx.x + sr[0 * FSTR + n];
        o.y = rx.y + sr[1 * FSTR + n];
        *(float2*)(out + a) = o;
    }
}

// ---------------------------------------------------------------------------
// EinFFT MLP with DFT4/IDFT4 over the NB axis folded in.
// ---------------------------------------------------------------------------
__global__ void __launch_bounds__(256) einfft_mlp_kernel(
        float* __restrict__ fR, float* __restrict__ fI,
        const float* __restrict__ cw1, const float* __restrict__ cb1,
        const float* __restrict__ cw2, const float* __restrict__ cb2) {
    __shared__ float sR[2048], sI[2048];
    __shared__ float tR[2048], tI[2048];
    int row0 = blockIdx.x * 8;
    int tid = threadIdx.x;
    for (int i = tid; i < 2048; i += 256) {
        sR[i] = fR[(size_t)row0 * DIMC + i];
        sI[i] = fI[(size_t)row0 * DIMC + i];
    }
    __syncthreads();

    const float sc = SQRT_INV_8192;
    #pragma unroll
    for (int g = tid; g < 512; g += 256) {
        int r = g >> 6, s = g & 63;
        int p = r * 256 + s;
        float r0 = sR[p],       i0 = sI[p];
        float r1 = sR[p + 64],  i1 = sI[p + 64];
        float r2 = sR[p + 128], i2 = sI[p + 128];
        float r3 = sR[p + 192], i3 = sI[p + 192];
        sR[p]       = (r0 + r1 + r2 + r3) * sc;
        sI[p]       = (i0 + i1 + i2 + i3) * sc;
        sR[p + 64]  = (r0 + i1 - r2 - i3) * sc;
        sI[p + 64]  = (i0 - r1 - i2 + r3) * sc;
        sR[p + 128] = (r0 - r1 + r2 - r3) * sc;
        sI[p + 128] = (i0 - i1 + i2 - i3) * sc;
        sR[p + 192] = (r0 - i1 - r2 + i3) * sc;
        sI[p + 192] = (i0 + r1 - i2 - r3) * sc;
    }
    __syncthreads();

    int k = tid >> 6, o = tid & 63;

    {
        const float* w0 = cw1 + k * 4096;
        const float* w1 = cw1 + 16384 + k * 4096;
        float bR = cb1[k * 64 + o];
        float bI = cb1[256 + k * 64 + o];
        float aR[8], aI[8];
        #pragma unroll
        for (int r = 0; r < 8; r++) { aR[r] = bR; aI[r] = bI; }
        for (int dd = 0; dd < 64; dd++) {
            float wa = w0[dd * 64 + o];
            float wb = w1[dd * 64 + o];
            int sb = k * 64 + dd;
            #pragma unroll
            for (int r = 0; r < 8; r++) {
                float xr = sR[r * 256 + sb];
                float xi = sI[r * 256 + sb];
                aR[r] = fmaf(xr, wa, fmaf(-xi, wb, aR[r]));
                aI[r] = fmaf(xr, wb, fmaf( xi, wa, aI[r]));
            }
        }
        #pragma unroll
        for (int r = 0; r < 8; r++) {
            tR[r * 256 + tid] = fmaxf(aR[r], 0.0f);
            tI[r * 256 + tid] = fmaxf(aI[r], 0.0f);
        }
    }
    __syncthreads();

    {
        const float* w0 = cw2 + k * 4096;
        const float* w1 = cw2 + 16384 + k * 4096;
        float bR = cb2[k * 64 + o];
        float bI = cb2[256 + k * 64 + o];
        float aR[8], aI[8];
        #pragma unroll
        for (int r = 0; r < 8; r++) { aR[r] = bR; aI[r] = bI; }
        for (int dd = 0; dd < 64; dd++) {
            float wa = w0[dd * 64 + o];
            float wb = w1[dd * 64 + o];
            int sb = k * 64 + dd;
            #pragma unroll
            for (int r = 0; r < 8; r++) {
                float xr = tR[r * 256 + sb];
                float xi = tI[r * 256 + sb];
                aR[r] = fmaf(xr, wa, fmaf(-xi, wb, aR[r]));
                aI[r] = fmaf(xr, wb, fmaf( xi, wa, aI[r]));
            }
        }
        #pragma unroll
        for (int r = 0; r < 8; r++) {
            float vR = aR[r], vI = aI[r];
            vR = (vR > LAMBDA_SS) ? vR - LAMBDA_SS
                 : ((vR < -LAMBDA_SS) ? vR + LAMBDA_SS : 0.0f);
            vI = (vI > LAMBDA_SS) ? vI - LAMBDA_SS
                 : ((vI < -LAMBDA_SS) ? vI + LAMBDA_SS : 0.0f);
            sR[r * 256 + tid] = vR;
            sI[r * 256 + tid] = vI;
        }
    }
    __syncthreads();

    #pragma unroll
    for (int g = tid; g < 512; g += 256) {
        int r = g >> 6, s = g & 63;
        int p = r * 256 + s;
        float R0 = sR[p],       I0 = sI[p];
        float R1 = sR[p + 64],  I1 = sI[p + 64];
        float R2 = sR[p + 128], I2 = sI[p + 128];
        float R3 = sR[p + 192], I3 = sI[p + 192];
        sR[p]       = (R0 + R1 + R2 + R3) * sc;
        sI[p]       = (I0 + I1 + I2 + I3) * sc;
        sR[p + 64]  = (R0 - I1 - R2 + I3) * sc;
        sI[p + 64]  = (I0 + R1 - I2 - R3) * sc;
        sR[p + 128] = (R0 - R1 + R2 - R3) * sc;
        sI[p + 128] = (I0 - I1 + I2 - I3) * sc;
        sR[p + 192] = (R0 + I1 - R2 - I3) * sc;
        sI[p + 192] = (I0 - R1 - I2 + R3) * sc;
    }
    __syncthreads();

    for (int i = tid; i < 2048; i += 256) {
        fR[(size_t)row0 * DIMC + i] = sR[i];
        fI[(size_t)row0 * DIMC + i] = sI[i];
    }
}

// ---------------------------------------------------------------------------
// Launch
// ---------------------------------------------------------------------------
extern "C" void kernel_launch(void* const* d_in, const int* in_sizes, int n_in,
                              void* d_out, int out_size) {
    const float* x         = (const float*)d_in[0];
    const float* norm1_w   = (const float*)d_in[1];
    const float* norm1_b   = (const float*)d_in[2];
    const float* in_proj_w = (const float*)d_in[3];
    const float* conv_w    = (const float*)d_in[4];
    const float* conv_b    = (const float*)d_in[5];
    const float* x_proj_w  = (const float*)d_in[6];
    const float* dt_proj_w = (const float*)d_in[7];
    const float* dt_proj_b = (const float*)d_in[8];
    const float* A_log     = (const float*)d_in[9];
    const float* Dvec      = (const float*)d_in[10];
    const float* out_proj_w= (const float*)d_in[11];
    const float* norm2_w   = (const float*)d_in[12];
    const float* norm2_b   = (const float*)d_in[13];
    const float* cw1       = (const float*)d_in[14];
    const float* cb1       = (const float*)d_in[15];
    const float* cw2       = (const float*)d_in[16];
    const float* cb2       = (const float*)d_in[17];
    float* out = (float*)d_out;

    void* sp = nullptr;
    cudaGetSymbolAddress(&sp, SCRATCH);
    float* S = (float*)sp;
    float* s_xn   = S + O_XN;
    float* s_xz   = S + O_XZ;
    float* s_xc   = S + O_XC;
    float* s_xdbl = S + O_XDBL;
    float* s_y    = S + O_Y;
    float* s_x1   = S + O_X1;
    float* s_xn2  = S + O_XN2;
    float* s_fr   = S + O_FR;
    float* s_fi   = S + O_FI;

    static int attr_done = 0;
    if (!attr_done) {
        cudaFuncSetAttribute(fft_fwd_kernel,
                             cudaFuncAttributeMaxDynamicSharedMemorySize, FFT_SMEM);
        cudaFuncSetAttribute(fft_inv_kernel,
                             cudaFuncAttributeMaxDynamicSharedMemorySize, FFT_SMEM);
        cudaFuncSetAttribute(gemm_tf32,
                             cudaFuncAttributeMaxDynamicSharedMemorySize, GEMM_SMEM);
        attr_done = 1;
    }

    // 1) LN1
    ln_kernel<<<NTOK / 8, 256>>>(x, norm1_w, norm1_b, s_xn);
    // 2) in_proj
    gemm_tf32<<<dim3((2 * DI) / GBN, NTOK / GBM), 128, GEMM_SMEM>>>(
        s_xn, in_proj_w, nullptr, s_xz, NTOK, 2 * DI, DIMC);
    // 3) conv + silu
    conv_silu_kernel<<<(NTOK * DI) / 256, 256>>>(s_xz, conv_w, conv_b, s_xc);
    // 4) x_proj
    gemm_tf32<<<dim3((XDBLW + GBN - 1) / GBN, NTOK / GBM), 128, GEMM_SMEM>>>(
        s_xc, x_proj_w, nullptr, s_xdbl, NTOK, XDBLW, DI);
    // 5) selective scan (fused dt + D-skip + silu(z) gate)
    scan_kernel<<<BATCH * (DI / 8), 256>>>(s_xdbl, s_xc, s_xz, A_log, Dvec,
                                           dt_proj_w, dt_proj_b, s_y);
    // 6) out_proj + residual
    gemm_tf32<<<dim3(DIMC / GBN, NTOK / GBM), 128, GEMM_SMEM>>>(
        s_y, out_proj_w, x, s_x1, NTOK, DIMC, DI);
    // 7) LN2
    ln_kernel<<<NTOK / 8, 256>>>(s_x1, norm2_w, norm2_b, s_xn2);
    // 8) forward FFT (2 ch/block, 256 blocks)
    fft_fwd_kernel<<<256, 512, FFT_SMEM>>>(s_xn2, s_fr, s_fi);
    // 9) fused EinFFT MLP (DFT4 + relu + softshrink + IDFT4)
    einfft_mlp_kernel<<<NTOK / 8, 256>>>(s_fr, s_fi, cw1, cb1, cw2, cb2);
    // 10) inverse FFT + residual -> out
    fft_inv_kernel<<<256, 512, FFT_SMEM>>>(s_fr, s_fi, s_x1, out);
}